// round 6
// baseline (speedup 1.0000x reference)
#include <cuda_runtime.h>

#define HW    2048
#define HW2   1024
#define MASK  2047
#define BATCH 4
#define SY    32
#define WPB   4
#define NSTRIP 36          // 36*60 = 2160 >= 2048
#define NBY   (HW / SY)    // 64

// scalar constants
#define C0f     0.3623577545f      // cos(1.2)
#define S0f     0.9320390860f      // sin(1.2)
#define C02f    0.7247155090f      // 2*C0
#define S02f    1.8640781720f      // 2*S0
#define NS0f    (-0.9320390860f)
#define EPBf    0.19245009f        // EB  * sqrt(KB)
#define EPDf    0.0038490018f      // EBD * sqrt(KB)
#define PCCf    (-0.0057735027f)   // M6EBD * KA / sqrt(KB)
#define KTf     0.1111111111f      // DT/dx^2
#define KAPf    1.8f
#define DTTAUf  0.3333333333f
#define APIXf   0.2864788976f      // alpha/pi
#define PIO2f   1.5707963268f

typedef unsigned long long u64;

// ---- packed f32x2 helpers ----
__device__ __forceinline__ u64 pk(float lo, float hi) {
    u64 r; asm("mov.b64 %0, {%1, %2};" : "=l"(r) : "f"(lo), "f"(hi)); return r;
}
__device__ __forceinline__ void upk(u64 v, float& lo, float& hi) {
    asm("mov.b64 {%0, %1}, %2;" : "=f"(lo), "=f"(hi) : "l"(v));
}
__device__ __forceinline__ u64 fma2v(u64 a, u64 b, u64 c) {
    u64 d; asm("fma.rn.f32x2 %0, %1, %2, %3;" : "=l"(d) : "l"(a), "l"(b), "l"(c)); return d;
}
__device__ __forceinline__ u64 mul2v(u64 a, u64 b) {
    u64 d; asm("mul.rn.f32x2 %0, %1, %2;" : "=l"(d) : "l"(a), "l"(b)); return d;
}
__device__ __forceinline__ u64 add2v(u64 a, u64 b) {
    u64 d; asm("add.rn.f32x2 %0, %1, %2;" : "=l"(d) : "l"(a), "l"(b)); return d;
}
__device__ __forceinline__ u64 neg2v(u64 a) { return a ^ 0x8000000080000000ULL; }

struct K2 {
    u64 M1, M4, C0v, NS0v, C02v, S02v, EPB, EPD, PCC;
    u64 GAMp, GAMn, APIX, MHALF, DTTAU, KAP, KT;
    u64 A9, A7, A5, A3, A1;
};

// stage1 on a packed column pair; P1/P2 pre-scaled by KA, E2 by KB
__device__ __forceinline__ void stage1v(u64 L, u64 R, u64 dn, u64 up,
                                        u64& P1, u64& P2, u64& E2, const K2& K)
{
    u64 dx   = fma2v(L, K.M1, R);            // R - L
    u64 dy   = fma2v(dn, K.M1, up);          // up - dn
    u64 ndy  = neg2v(dy);
    u64 dx2  = mul2v(dx, dx);
    u64 r2   = fma2v(dy, dy, dx2);
    u64 a2   = fma2v(dy, ndy, dx2);          // dx^2 - dy^2
    u64 bh   = mul2v(dx, dy);
    u64 b2   = add2v(bh, bh);                // 2 dx dy
    u64 a3   = fma2v(b2, ndy, mul2v(a2, dx));
    u64 b3   = fma2v(b2, dx,  mul2v(a2, dy));
    u64 nb3  = neg2v(b3);
    u64 Az   = fma2v(b3, nb3, mul2v(a3, a3));   // Re(z^6)
    u64 Bh   = mul2v(a3, b3);                   // Im(z^6)/2
    u64 r4   = mul2v(r2, r2);
    u64 r6   = mul2v(r4, r2);
    float f0, f1; upk(r6, f0, f1);
    float i0 = __fdividef(1.0f, fmaxf(f0, 1e-30f));
    float i1 = __fdividef(1.0f, fmaxf(f1, 1e-30f));
    u64 ir6  = pk(i0, i1);
    u64 u    = mul2v(fma2v(Bh, K.S02v, mul2v(Az, K.C0v)), ir6);   // cos(6(th-th0))
    u64 v    = mul2v(fma2v(Bh, K.C02v, mul2v(Az, K.NS0v)), ir6);  // sin(6(th-th0))
    u64 ep   = fma2v(K.EPD, u, K.EPB);       // eps * sqrt(KB)
    u64 pc   = mul2v(ep, mul2v(K.PCC, v));   // eps*eps_deriv*KA
    P1 = mul2v(pc, dx);
    P2 = mul2v(pc, ndy);
    E2 = mul2v(ep, ep);
}

template<bool WRAP>
__device__ __forceinline__ void sweep_body(const float* __restrict__ phi,
                                           const float* __restrict__ tempr,
                                           float* __restrict__ out,
                                           int y0)
{
    const unsigned FULL = 0xffffffffu;
    const int lane  = threadIdx.x & 31;
    const int wid   = threadIdx.x >> 5;
    const int strip = blockIdx.x * WPB + wid;       // 0..35
    const int b     = blockIdx.z;
    const int lm    = lane - 1;
    const int lp    = lane + 1;

    K2 K;
    K.M1    = pk(-1.0f, -1.0f);
    K.M4    = pk(-4.0f, -4.0f);
    K.C0v   = pk(C0f, C0f);
    K.NS0v  = pk(NS0f, NS0f);
    K.C02v  = pk(C02f, C02f);
    K.S02v  = pk(S02f, S02f);
    K.EPB   = pk(EPBf, EPBf);
    K.EPD   = pk(EPDf, EPDf);
    K.PCC   = pk(PCCf, PCCf);
    K.GAMp  = pk(10.0f, 10.0f);
    K.GAMn  = pk(-10.0f, -10.0f);
    K.APIX  = pk(APIXf, APIXf);
    K.MHALF = pk(-0.5f, -0.5f);
    K.DTTAU = pk(DTTAUf, DTTAUf);
    K.KAP   = pk(KAPf, KAPf);
    K.KT    = pk(KTf, KTf);
    K.A9    = pk(-0.01172120f, -0.01172120f);
    K.A7    = pk( 0.05265332f,  0.05265332f);
    K.A5    = pk(-0.11643287f, -0.11643287f);
    K.A3    = pk( 0.19354346f,  0.19354346f);
    K.A1    = pk(-0.33262347f, -0.33262347f);
    const u64 A0 = pk(0.99997726f, 0.99997726f);

    const int xc = (strip * 60 - 2 + 2 * lane) & MASK;
    const size_t base = (size_t)b * HW * HW;
    const u64* __restrict__ pb = (const u64*)(phi   + base) + (xc >> 1);
    const u64* __restrict__ tb = (const u64*)(tempr + base) + (xc >> 1);
    u64* __restrict__ po = (u64*)(out + base) + (xc >> 1);
    u64* __restrict__ to = (u64*)(out + (size_t)BATCH * HW * HW + base) + (xc >> 1);

#define PROW(r) pb[((r) & MASK) * HW2]
#define TROW(r) tb[((r) & MASK) * HW2]

    // prologue (wrap-safe via mask)
    u64 pm2 = PROW(y0 - 2), pm1 = PROW(y0 - 1), p0 = PROW(y0);
    u64 pp1 = PROW(y0 + 1), pp2 = PROW(y0 + 2), pp3 = PROW(y0 + 3);
    u64 tm1 = TROW(y0 - 1), t0 = TROW(y0);
    u64 tp1 = TROW(y0 + 1), tp2 = TROW(y0 + 2);

    u64 P1m, P1c, P2c, E2c;
    {
        float ax, ay; upk(pm1, ax, ay);
        float Lc = __shfl_sync(FULL, ay, lm);
        float Rc = __shfl_sync(FULL, ax, lp);
        u64 d0, d1;
        stage1v(pk(Lc, ax), pk(ay, Rc), pm2, p0, P1m, d0, d1, K);
    }
    {
        float ax, ay; upk(p0, ax, ay);
        float Lc = __shfl_sync(FULL, ay, lm);
        float Rc = __shfl_sync(FULL, ax, lp);
        stage1v(pk(Lc, ax), pk(ay, Rc), pm1, pp1, P1c, P2c, E2c, K);
    }

    const bool wr = (lane >= 1) && (lane <= 30);

    const u64* pld = pb + (size_t)(y0 + 4) * HW2;
    const u64* tld = tb + (size_t)(y0 + 3) * HW2;
    u64* por = po + (size_t)y0 * HW2;
    u64* tor = to + (size_t)y0 * HW2;

    #pragma unroll 4
    for (int i = 0; i < SY; ++i) {
        u64 pp4, tp3;
        if (WRAP) {
            pp4 = PROW(y0 + i + 4);
            tp3 = TROW(y0 + i + 3);
        } else {
            pp4 = *pld;  pld += HW2;
            tp3 = *tld;  tld += HW2;
        }

        // stage1 at row y+1
        u64 P1n, P2n, E2n;
        {
            float ax, ay; upk(pp1, ax, ay);
            float Lc = __shfl_sync(FULL, ay, lm);
            float Rc = __shfl_sync(FULL, ax, lp);
            stage1v(pk(Lc, ax), pk(ay, Rc), p0, pp2, P1n, P2n, E2n, K);
        }

        // x-neighbor shuffles for stage2
        float p0x, p0y;  upk(p0,  p0x, p0y);
        float t0x, t0y;  upk(t0,  t0x, t0y);
        float P2x, P2y;  upk(P2c, P2x, P2y);
        float Lp  = __shfl_sync(FULL, p0y, lm);
        float Rp  = __shfl_sync(FULL, p0x, lp);
        float Lt  = __shfl_sync(FULL, t0y, lm);
        float Rt  = __shfl_sync(FULL, t0x, lp);
        float LP2 = __shfl_sync(FULL, P2y, lm);
        float RP2 = __shfl_sync(FULL, P2x, lp);

        u64 lapp = add2v(add2v(pp1, pm1), add2v(pk(Lp, p0x), pk(p0y, Rp)));
        lapp = fma2v(p0, K.M4, lapp);
        u64 lapt = add2v(add2v(tp1, tm1), add2v(pk(Lt, t0x), pk(t0y, Rt)));
        lapt = fma2v(t0, K.M4, lapt);

        u64 term = add2v(fma2v(P1m, K.M1, P1n),
                         fma2v(pk(LP2, P2x), K.M1, pk(P2y, RP2)));

        // atan term
        u64 g2 = fma2v(t0, K.GAMn, K.GAMp);       // 10*(1 - T)
        float g0, g1; upk(g2, g0, g1);
        float i0 = __fdividef(1.0f, g0);
        float i1 = __fdividef(1.0f, g1);
        float w0 = fminf(g0, i0);
        float w1 = fminf(g1, i1);
        u64 wv = pk(w0, w1);
        u64 w2 = mul2v(wv, wv);
        u64 pp = fma2v(w2, K.A9, K.A7);
        pp = fma2v(w2, pp, K.A5);
        pp = fma2v(w2, pp, K.A3);
        pp = fma2v(w2, pp, K.A1);
        pp = fma2v(w2, pp, A0);
        pp = mul2v(pp, wv);
        float q0, q1; upk(pp, q0, q1);
        float at0 = (g0 > 1.0f) ? (PIO2f - q0) : q0;
        float at1 = (g1 > 1.0f) ? (PIO2f - q1) : q1;
        u64 atv = pk(at0, at1);

        u64 marg = fma2v(K.APIX, atv, add2v(p0, K.MHALF));   // phi-0.5+m
        u64 qv   = fma2v(neg2v(p0), p0, p0);                 // phi(1-phi)
        u64 dphi = fma2v(E2c, lapp, term);
        dphi = fma2v(mul2v(qv, marg), K.DTTAU, dphi);

        u64 outp = add2v(p0, dphi);
        u64 outt = fma2v(K.KAP, dphi, fma2v(K.KT, lapt, t0));

        if (wr) {
            *por = outp;
            *tor = outt;
        }
        por += HW2;
        tor += HW2;

        pm1 = p0;  p0 = pp1;  pp1 = pp2;  pp2 = pp3;  pp3 = pp4;
        tm1 = t0;  t0 = tp1;  tp1 = tp2;  tp2 = tp3;
        P1m = P1c; P1c = P1n; P2c = P2n; E2c = E2n;
    }
#undef PROW
#undef TROW
}

__global__ __launch_bounds__(WPB * 32, 5)
void dendrite_sweep4(const float* __restrict__ phi,
                     const float* __restrict__ tempr,
                     float* __restrict__ out)
{
    const int by = blockIdx.y;
    const int y0 = by * SY;
    if (by == 0 || by == NBY - 1) {
        sweep_body<true>(phi, tempr, out, y0);
    } else {
        sweep_body<false>(phi, tempr, out, y0);
    }
}

extern "C" void kernel_launch(void* const* d_in, const int* in_sizes, int n_in,
                              void* d_out, int out_size)
{
    const float* phi   = (const float*)d_in[0];
    const float* tempr = (const float*)d_in[1];
    float* out = (float*)d_out;

    dim3 block(WPB * 32);
    dim3 grid(NSTRIP / WPB, NBY, BATCH);   // (9, 64, 4) = 2304 CTAs
    dendrite_sweep4<<<grid, block>>>(phi, tempr, out);
}

// round 7
// speedup vs baseline: 1.1560x; 1.1560x over previous
#include <cuda_runtime.h>

#define HW    2048
#define HW2   1024
#define MASK  2047
#define BATCH 4
#define SY    32
#define WPB   5
#define NSTRIP 35          // 35*60 = 2100 >= 2048; overlap strips write identical wrapped values
#define NBY   (HW / SY)    // 64

// folded constants
#define C0f     0.3623577545f      // cos(1.2)
#define S0f     0.9320390860f      // sin(1.2)
#define S02f    1.8640781720f      // 2*sin(1.2)
#define C02f    0.7247155090f      // 2*cos(1.2)
#define EPBf    0.19245009f        // EB  * sqrt(KB),  KB = (DT/TAU)/dx^2
#define EPDf    0.0038490018f      // EBD * sqrt(KB)
#define PCCf    (-0.0057735027f)   // M6EBD * KA / sqrt(KB),  KA = (DT/TAU)/(2dx)^2
#define KTf     0.1111111111f      // DT/dx^2
#define KAPf    1.8f
#define DTTAUf  0.3333333333f
#define APIXf   0.2864788976f      // alpha/pi
#define PIO2f   1.5707963268f

// stage1: P1/P2 pre-scaled by KA, E2 pre-scaled by KB (via eps' = eps*sqrt(KB))
__device__ __forceinline__ void stage1(float L, float R, float dn, float up,
                                       float& P1, float& P2, float& E2)
{
    float dx  = R - L;
    float dy  = up - dn;
    float dx2 = dx * dx;
    float dy2 = dy * dy;
    float r2  = dx2 + dy2;
    float t1  = fmaf(-3.0f, dy2, dx2);       // dx^2 - 3 dy^2
    float t2  = fmaf( 3.0f, dx2, -dy2);      // 3 dx^2 - dy^2
    float a3  = dx * t1;                     // Re(z^3)
    float b3  = dy * t2;                     // Im(z^3)
    float Az  = fmaf(a3, a3, -(b3 * b3));    // Re(z^6)
    float Bh  = a3 * b3;                     // Im(z^6)/2
    float r6  = r2 * r2 * r2;
    float ir6 = __fdividef(1.0f, fmaxf(r6, 1e-30f));
    float u   = fmaf(Az, C0f,  (Bh * S02f)) * ir6;   // cos(6(theta-theta0))
    float v   = fmaf(Bh, C02f, -(Az * S0f)) * ir6;   // sin(6(theta-theta0))
    float ep  = fmaf(EPDf, u, EPBf);        // eps * sqrt(KB)
    float pc  = ep * (PCCf * v);            // eps*eps_deriv*KA
    P1 =  pc * dx;
    P2 = -pc * dy;
    E2 = ep * ep;
}

// atan for g in (0, 10]; 3-term odd minimax on [0,1] (err ~6e-4 rad, well
// within the 1e-3 output gate after the 0.043 sensitivity factor)
__device__ __forceinline__ float atan_pos(float g)
{
    float inv = __fdividef(1.0f, g);
    float w   = fminf(g, inv);
    float w2  = w * w;
    float p   = fmaf(w2, 0.0793331f, -0.2886680f);
    p = fmaf(w2, p, 0.9953545f);
    p = p * w;
    return (g > 1.0f) ? (PIO2f - p) : p;
}

template<bool WRAP>
__device__ __forceinline__ void sweep_body(const float* __restrict__ phi,
                                           const float* __restrict__ tempr,
                                           float* __restrict__ out,
                                           int y0)
{
    const unsigned FULL = 0xffffffffu;
    const int lane  = threadIdx.x & 31;
    const int wid   = threadIdx.x >> 5;
    const int strip = blockIdx.x * WPB + wid;       // 0..34
    const int b     = blockIdx.z;
    const int lm    = lane - 1;
    const int lp    = lane + 1;

    const int xc = (strip * 60 - 2 + 2 * lane) & MASK;
    const size_t base = (size_t)b * HW * HW;
    const float2* __restrict__ pb = (const float2*)(phi   + base) + (xc >> 1);
    const float2* __restrict__ tb = (const float2*)(tempr + base) + (xc >> 1);
    float2* __restrict__ po = (float2*)(out + base) + (xc >> 1);
    float2* __restrict__ to = (float2*)(out + (size_t)BATCH * HW * HW + base) + (xc >> 1);

#define PROW(r) pb[((r) & MASK) * HW2]
#define TROW(r) tb[((r) & MASK) * HW2]

    // prologue (wrap-safe via mask; one-time)
    float2 pm2 = PROW(y0 - 2), pm1 = PROW(y0 - 1), p0 = PROW(y0);
    float2 pp1 = PROW(y0 + 1), pp2 = PROW(y0 + 2), pp3 = PROW(y0 + 3);
    float2 tm1 = TROW(y0 - 1), t0 = TROW(y0);
    float2 tp1 = TROW(y0 + 1), tp2 = TROW(y0 + 2);

    float2 P1m, P1c, P2c, E2c;
    {
        float Lc = __shfl_sync(FULL, pm1.y, lm);
        float Rc = __shfl_sync(FULL, pm1.x, lp);
        float d0, d1;
        stage1(Lc,    pm1.y, pm2.x, p0.x, P1m.x, d0, d1);
        stage1(pm1.x, Rc,    pm2.y, p0.y, P1m.y, d0, d1);
    }
    {
        float Lc = __shfl_sync(FULL, p0.y, lm);
        float Rc = __shfl_sync(FULL, p0.x, lp);
        stage1(Lc,   p0.y, pm1.x, pp1.x, P1c.x, P2c.x, E2c.x);
        stage1(p0.x, Rc,   pm1.y, pp1.y, P1c.y, P2c.y, E2c.y);
    }

    const bool wr = (lane >= 1) && (lane <= 30);

    // marching pointers (interior path: no mask, no per-iter index math)
    const float2* pld = pb + (size_t)(y0 + 4) * HW2;
    const float2* tld = tb + (size_t)(y0 + 3) * HW2;
    float2* por = po + (size_t)y0 * HW2;
    float2* tor = to + (size_t)y0 * HW2;

    #pragma unroll 4
    for (int i = 0; i < SY; ++i) {
        float2 pp4, tp3;
        if (WRAP) {
            pp4 = PROW(y0 + i + 4);
            tp3 = TROW(y0 + i + 3);
        } else {
            pp4 = *pld;  pld += HW2;
            tp3 = *tld;  tld += HW2;
        }

        float2 P1n, P2n, E2n;
        {
            float Lc = __shfl_sync(FULL, pp1.y, lm);
            float Rc = __shfl_sync(FULL, pp1.x, lp);
            stage1(Lc,    pp1.y, p0.x, pp2.x, P1n.x, P2n.x, E2n.x);
            stage1(pp1.x, Rc,    p0.y, pp2.y, P1n.y, P2n.y, E2n.y);
        }

        float Lp  = __shfl_sync(FULL, p0.y,  lm);
        float Rp  = __shfl_sync(FULL, p0.x,  lp);
        float Lt  = __shfl_sync(FULL, t0.y,  lm);
        float Rt  = __shfl_sync(FULL, t0.x,  lp);
        float LP2 = __shfl_sync(FULL, P2c.y, lm);
        float RP2 = __shfl_sync(FULL, P2c.x, lp);

        float2 outp, outt;
        {   // column xc
            float lapp = (pp1.x + pm1.x) + (Lp + p0.y);
            lapp = fmaf(p0.x, -4.0f, lapp);
            float lapt = (tp1.x + tm1.x) + (Lt + t0.y);
            lapt = fmaf(t0.x, -4.0f, lapt);
            float term = (P1n.x - P1m.x) + (P2c.y - LP2);   // KA pre-folded
            float at   = atan_pos(fmaf(t0.x, -10.0f, 10.0f));
            float marg = fmaf(APIXf, at, p0.x - 0.5f);
            float q    = fmaf(-p0.x, p0.x, p0.x);
            float dphi = fmaf(E2c.x, lapp, term);           // KB pre-folded
            dphi = fmaf(q * marg, DTTAUf, dphi);
            outp.x = p0.x + dphi;
            outt.x = fmaf(KAPf, dphi, fmaf(KTf, lapt, t0.x));
        }
        {   // column xc+1
            float lapp = (pp1.y + pm1.y) + (p0.x + Rp);
            lapp = fmaf(p0.y, -4.0f, lapp);
            float lapt = (tp1.y + tm1.y) + (t0.x + Rt);
            lapt = fmaf(t0.y, -4.0f, lapt);
            float term = (P1n.y - P1m.y) + (RP2 - P2c.x);
            float at   = atan_pos(fmaf(t0.y, -10.0f, 10.0f));
            float marg = fmaf(APIXf, at, p0.y - 0.5f);
            float q    = fmaf(-p0.y, p0.y, p0.y);
            float dphi = fmaf(E2c.y, lapp, term);
            dphi = fmaf(q * marg, DTTAUf, dphi);
            outp.y = p0.y + dphi;
            outt.y = fmaf(KAPf, dphi, fmaf(KTf, lapt, t0.y));
        }

        if (wr) {
            *por = outp;
            *tor = outt;
        }
        por += HW2;
        tor += HW2;

        pm1 = p0;  p0 = pp1;  pp1 = pp2;  pp2 = pp3;  pp3 = pp4;
        tm1 = t0;  t0 = tp1;  tp1 = tp2;  tp2 = tp3;
        P1m = P1c; P1c = P1n; P2c = P2n; E2c = E2n;
    }
#undef PROW
#undef TROW
}

__global__ __launch_bounds__(WPB * 32, 6)
void dendrite_sweep5(const float* __restrict__ phi,
                     const float* __restrict__ tempr,
                     float* __restrict__ out)
{
    const int by = blockIdx.y;
    const int y0 = by * SY;
    if (by == 0 || by == NBY - 1) {
        sweep_body<true>(phi, tempr, out, y0);
    } else {
        sweep_body<false>(phi, tempr, out, y0);
    }
}

extern "C" void kernel_launch(void* const* d_in, const int* in_sizes, int n_in,
                              void* d_out, int out_size)
{
    const float* phi   = (const float*)d_in[0];
    const float* tempr = (const float*)d_in[1];
    float* out = (float*)d_out;

    dim3 block(WPB * 32);
    dim3 grid(NSTRIP / WPB, NBY, BATCH);   // (7, 64, 4) = 1792 CTAs
    dendrite_sweep5<<<grid, block>>>(phi, tempr, out);
}

// round 8
// speedup vs baseline: 1.1962x; 1.0347x over previous
#include <cuda_runtime.h>

#define HW    2048
#define HW2   1024
#define MASK  2047
#define BATCH 4
#define SY    32
#define WPB   4
#define NSTRIP 36          // 36*60 = 2160 >= 2048; overlap strips rewrite identical wrapped values
#define NBY   (HW / SY)    // 64

// folded constants
#define C0f     0.3623577545f      // cos(1.2)
#define S0f     0.9320390860f      // sin(1.2)
#define S02f    1.8640781720f      // 2*sin(1.2)
#define C02f    0.7247155090f      // 2*cos(1.2)
#define EPBf    0.19245009f        // EB  * sqrt(KB),  KB = (DT/TAU)/dx^2
#define EPDf    0.0038490018f      // EBD * sqrt(KB)
#define PCCf    (-0.0057735027f)   // M6EBD * KA / sqrt(KB),  KA = (DT/TAU)/(2dx)^2
#define KTf     0.1111111111f      // DT/dx^2
#define KAPf    1.8f
#define DTTAUf  0.3333333333f
#define APIXf   0.2864788976f      // alpha/pi
#define PIO2f   1.5707963268f

// stage1: P1/P2 pre-scaled by KA, E2 pre-scaled by KB (via eps' = eps*sqrt(KB))
__device__ __forceinline__ void stage1(float L, float R, float dn, float up,
                                       float& P1, float& P2, float& E2)
{
    float dx  = R - L;
    float dy  = up - dn;
    float dx2 = dx * dx;
    float dy2 = dy * dy;
    float r2  = dx2 + dy2;
    float t1  = fmaf(-3.0f, dy2, dx2);       // dx^2 - 3 dy^2
    float t2  = fmaf( 3.0f, dx2, -dy2);      // 3 dx^2 - dy^2
    float a3  = dx * t1;                     // Re(z^3)
    float b3  = dy * t2;                     // Im(z^3)
    float Az  = fmaf(a3, a3, -(b3 * b3));    // Re(z^6)
    float Bh  = a3 * b3;                     // Im(z^6)/2
    float r6  = r2 * r2 * r2;
    float ir6 = __fdividef(1.0f, fmaxf(r6, 1e-30f));
    float u   = fmaf(Az, C0f,  (Bh * S02f)) * ir6;   // cos(6(theta-theta0))
    float v   = fmaf(Bh, C02f, -(Az * S0f)) * ir6;   // sin(6(theta-theta0))
    float ep  = fmaf(EPDf, u, EPBf);        // eps * sqrt(KB)
    float pc  = ep * (PCCf * v);            // eps*eps_deriv*KA
    P1 =  pc * dx;
    P2 = -pc * dy;
    E2 = ep * ep;
}

// atan for g in (0, 10]; 3-term odd minimax on [0,1] (err ~6e-4 rad)
__device__ __forceinline__ float atan_pos(float g)
{
    float inv = __fdividef(1.0f, g);
    float w   = fminf(g, inv);
    float w2  = w * w;
    float p   = fmaf(w2, 0.0793331f, -0.2886680f);
    p = fmaf(w2, p, 0.9953545f);
    p = p * w;
    return (g > 1.0f) ? (PIO2f - p) : p;
}

template<bool WRAP>
__device__ __forceinline__ void sweep_body(const float* __restrict__ phi,
                                           const float* __restrict__ tempr,
                                           float* __restrict__ out,
                                           int y0)
{
    const unsigned FULL = 0xffffffffu;
    const int lane  = threadIdx.x & 31;
    const int wid   = threadIdx.x >> 5;
    const int strip = blockIdx.x * WPB + wid;       // 0..35
    const int b     = blockIdx.z;
    const int lm    = lane - 1;
    const int lp    = lane + 1;

    const int xc = (strip * 60 - 2 + 2 * lane) & MASK;
    const size_t base = (size_t)b * HW * HW;
    const float2* __restrict__ pb = (const float2*)(phi   + base) + (xc >> 1);
    const float2* __restrict__ tb = (const float2*)(tempr + base) + (xc >> 1);
    float2* __restrict__ po = (float2*)(out + base) + (xc >> 1);
    float2* __restrict__ to = (float2*)(out + (size_t)BATCH * HW * HW + base) + (xc >> 1);

#define PROW(r) pb[((r) & MASK) * HW2]
#define TROW(r) tb[((r) & MASK) * HW2]

    // prologue (wrap-safe via mask; one-time). pm2 is transient.
    float2 pm2 = PROW(y0 - 2), pm1 = PROW(y0 - 1), p0 = PROW(y0);
    float2 pp1 = PROW(y0 + 1), pp2 = PROW(y0 + 2);
    float2 tm1 = TROW(y0 - 1), t0 = TROW(y0), tp1 = TROW(y0 + 1);

    float2 P1m, P1c, P2c, E2c;
    {
        float Lc = __shfl_sync(FULL, pm1.y, lm);
        float Rc = __shfl_sync(FULL, pm1.x, lp);
        float d0, d1;
        stage1(Lc,    pm1.y, pm2.x, p0.x, P1m.x, d0, d1);
        stage1(pm1.x, Rc,    pm2.y, p0.y, P1m.y, d0, d1);
    }
    {
        float Lc = __shfl_sync(FULL, p0.y, lm);
        float Rc = __shfl_sync(FULL, p0.x, lp);
        stage1(Lc,   p0.y, pm1.x, pp1.x, P1c.x, P2c.x, E2c.x);
        stage1(p0.x, Rc,   pm1.y, pp1.y, P1c.y, P2c.y, E2c.y);
    }

    const bool wr = (lane >= 1) && (lane <= 30);

    // marching pointers (interior path: no mask, no per-iter index math)
    const float2* pld = pb + (size_t)(y0 + 3) * HW2;
    const float2* tld = tb + (size_t)(y0 + 2) * HW2;
    float2* por = po + (size_t)y0 * HW2;
    float2* tor = to + (size_t)y0 * HW2;

    #pragma unroll 4
    for (int i = 0; i < SY; ++i) {
        float2 pnew, tnew;
        if (WRAP) {
            pnew = PROW(y0 + i + 3);
            tnew = TROW(y0 + i + 2);
        } else {
            pnew = *pld;  pld += HW2;
            tnew = *tld;  tld += HW2;
        }

        float2 P1n, P2n, E2n;
        {
            float Lc = __shfl_sync(FULL, pp1.y, lm);
            float Rc = __shfl_sync(FULL, pp1.x, lp);
            stage1(Lc,    pp1.y, p0.x, pp2.x, P1n.x, P2n.x, E2n.x);
            stage1(pp1.x, Rc,    p0.y, pp2.y, P1n.y, P2n.y, E2n.y);
        }

        float Lp  = __shfl_sync(FULL, p0.y,  lm);
        float Rp  = __shfl_sync(FULL, p0.x,  lp);
        float Lt  = __shfl_sync(FULL, t0.y,  lm);
        float Rt  = __shfl_sync(FULL, t0.x,  lp);
        float LP2 = __shfl_sync(FULL, P2c.y, lm);
        float RP2 = __shfl_sync(FULL, P2c.x, lp);

        float2 outp, outt;
        {   // column xc
            float lapp = (pp1.x + pm1.x) + (Lp + p0.y);
            lapp = fmaf(p0.x, -4.0f, lapp);
            float lapt = (tp1.x + tm1.x) + (Lt + t0.y);
            lapt = fmaf(t0.x, -4.0f, lapt);
            float term = (P1n.x - P1m.x) + (P2c.y - LP2);   // KA pre-folded
            float at   = atan_pos(fmaf(t0.x, -10.0f, 10.0f));
            float marg = fmaf(APIXf, at, p0.x - 0.5f);
            float q    = fmaf(-p0.x, p0.x, p0.x);
            float dphi = fmaf(E2c.x, lapp, term);           // KB pre-folded
            dphi = fmaf(q * marg, DTTAUf, dphi);
            outp.x = p0.x + dphi;
            outt.x = fmaf(KAPf, dphi, fmaf(KTf, lapt, t0.x));
        }
        {   // column xc+1
            float lapp = (pp1.y + pm1.y) + (p0.x + Rp);
            lapp = fmaf(p0.y, -4.0f, lapp);
            float lapt = (tp1.y + tm1.y) + (t0.x + Rt);
            lapt = fmaf(t0.y, -4.0f, lapt);
            float term = (P1n.y - P1m.y) + (RP2 - P2c.x);
            float at   = atan_pos(fmaf(t0.y, -10.0f, 10.0f));
            float marg = fmaf(APIXf, at, p0.y - 0.5f);
            float q    = fmaf(-p0.y, p0.y, p0.y);
            float dphi = fmaf(E2c.y, lapp, term);
            dphi = fmaf(q * marg, DTTAUf, dphi);
            outp.y = p0.y + dphi;
            outt.y = fmaf(KAPf, dphi, fmaf(KTf, lapt, t0.y));
        }

        if (wr) {
            __stcs(por, outp);      // streaming: outputs never re-read
            __stcs(tor, outt);
        }
        por += HW2;
        tor += HW2;

        pm1 = p0;  p0 = pp1;  pp1 = pp2;  pp2 = pnew;
        tm1 = t0;  t0 = tp1;  tp1 = tnew;
        P1m = P1c; P1c = P1n; P2c = P2n; E2c = E2n;
    }
#undef PROW
#undef TROW
}

__global__ __launch_bounds__(WPB * 32, 8)
void dendrite_sweep6(const float* __restrict__ phi,
                     const float* __restrict__ tempr,
                     float* __restrict__ out)
{
    const int by = blockIdx.y;
    const int y0 = by * SY;
    if (by == 0 || by == NBY - 1) {
        sweep_body<true>(phi, tempr, out, y0);
    } else {
        sweep_body<false>(phi, tempr, out, y0);
    }
}

extern "C" void kernel_launch(void* const* d_in, const int* in_sizes, int n_in,
                              void* d_out, int out_size)
{
    const float* phi   = (const float*)d_in[0];
    const float* tempr = (const float*)d_in[1];
    float* out = (float*)d_out;

    dim3 block(WPB * 32);
    dim3 grid(NSTRIP / WPB, NBY, BATCH);   // (9, 64, 4) = 2304 CTAs
    dendrite_sweep6<<<grid, block>>>(phi, tempr, out);
}